// round 1
// baseline (speedup 1.0000x reference)
#include <cuda_runtime.h>
#include <cuda_bf16.h>

// Problem constants
#define BB 4
#define TT 2048
#define CC 1024
#define HH 16
#define DD 64
#define MM (BB*TT)          // 8192 rows
#define OUT_K  8388608      // offset of k in d_out (floats)
#define OUT_V 16777216      // offset of v in d_out (floats)

// Scratch (allocation-free rule: __device__ globals)
__device__ float g_q[BB*HH*TT*DD];    // q in [b,h,t,d] layout
__device__ float g_att[BB*TT*CC];     // attention output, [b,t,c] layout

// ---------------------------------------------------------------------------
// Tiled SGEMM: out = A[M x 1024] @ W[1024 x N] + bias
// BM=128, BN=128, BK=16, 256 threads, 8x8 per-thread microtile.
// mode 1: QKV — scatter q -> g_q, k -> out+OUT_K, v -> out+OUT_V ([b,h,t,d])
// mode 2: proj — A is g_att (param A ignored), plain row-major store to out
// ---------------------------------------------------------------------------
__global__ __launch_bounds__(256, 2)
void gemm_kernel(const float* __restrict__ A, const float* __restrict__ W,
                 const float* __restrict__ bias, float* __restrict__ out,
                 int N, int mode)
{
    __shared__ float As[16][132];   // transposed A tile, padded
    __shared__ float Bs[16][132];

    const float* Amat = (mode == 2) ? g_att : A;

    int tid = threadIdx.x;
    int m0 = blockIdx.y * 128;
    int n0 = blockIdx.x * 128;
    int tx = tid & 15, ty = tid >> 4;

    float acc[8][8];
    #pragma unroll
    for (int i = 0; i < 8; i++)
        #pragma unroll
        for (int j = 0; j < 8; j++) acc[i][j] = 0.f;

    for (int k0 = 0; k0 < CC; k0 += 16) {
        // load A tile (128 x 16), store transposed
        #pragma unroll
        for (int f = tid; f < 512; f += 256) {
            int row = f >> 2;            // 0..127
            int kc  = (f & 3) << 2;      // 0,4,8,12
            float4 v = *(const float4*)&Amat[(size_t)(m0 + row)*CC + k0 + kc];
            As[kc+0][row] = v.x; As[kc+1][row] = v.y;
            As[kc+2][row] = v.z; As[kc+3][row] = v.w;
        }
        // load B tile (16 x 128)
        #pragma unroll
        for (int f = tid; f < 512; f += 256) {
            int kr = f >> 5;             // 0..15
            int nc = (f & 31) << 2;      // 0..124
            *(float4*)&Bs[kr][nc] =
                *(const float4*)&W[(size_t)(k0 + kr)*N + n0 + nc];
        }
        __syncthreads();

        #pragma unroll
        for (int kk = 0; kk < 16; kk++) {
            float a[8], b[8];
            *(float4*)&a[0] = *(float4*)&As[kk][ty*8];
            *(float4*)&a[4] = *(float4*)&As[kk][ty*8 + 4];
            *(float4*)&b[0] = *(float4*)&Bs[kk][tx*8];
            *(float4*)&b[4] = *(float4*)&Bs[kk][tx*8 + 4];
            #pragma unroll
            for (int i = 0; i < 8; i++)
                #pragma unroll
                for (int j = 0; j < 8; j++)
                    acc[i][j] += a[i] * b[j];
        }
        __syncthreads();
    }

    if (mode == 2) {
        // plain row-major store with bias
        #pragma unroll
        for (int i = 0; i < 8; i++) {
            int m = m0 + ty*8 + i;
            #pragma unroll
            for (int j = 0; j < 8; j += 4) {
                int n = n0 + tx*8 + j;
                float4 v;
                v.x = acc[i][j+0] + bias[n+0];
                v.y = acc[i][j+1] + bias[n+1];
                v.z = acc[i][j+2] + bias[n+2];
                v.w = acc[i][j+3] + bias[n+3];
                *(float4*)&out[(size_t)m*N + n] = v;
            }
        }
    } else {
        // QKV scatter: n in [0,3072): sel = n/1024, c = n%1024, h = c/64, d = c%64
        #pragma unroll
        for (int i = 0; i < 8; i++) {
            int m = m0 + ty*8 + i;
            int b = m >> 11;             // /T
            int t = m & 2047;
            #pragma unroll
            for (int j = 0; j < 8; j++) {
                int n = n0 + tx*8 + j;
                float val = acc[i][j] + bias[n];
                int sel = n >> 10;
                int c = n & 1023;
                int h = c >> 6, d = c & 63;
                size_t idx = ((size_t)(b*HH + h)*TT + t)*DD + d;
                if (sel == 0)      g_q[idx] = val;
                else if (sel == 1) out[OUT_K + idx] = val;
                else               out[OUT_V + idx] = val;
            }
        }
    }
}

// ---------------------------------------------------------------------------
// Causal flash attention. One CTA = 128 q-rows of one (b,h); one thread = one
// q-row (q and o accumulator fully in registers). K/V tiles (64 x 64) staged
// in SMEM, read warp-uniform -> broadcast LDS.128. Online softmax in chunks
// of 16 columns. Only k-tiles with k <= q processed (causal).
// ---------------------------------------------------------------------------
__global__ __launch_bounds__(128)
void attn_kernel(const float* __restrict__ kbuf, const float* __restrict__ vbuf)
{
    __shared__ float Ks[64][64];
    __shared__ float Vs[64][64];

    int qt  = blockIdx.x;           // q tile: 0..15
    int bh  = blockIdx.y;           // 0..63
    int tid = threadIdx.x;          // row within tile
    int qg  = qt*128 + tid;         // global q position
    const float scale = 0.125f;     // 1/sqrt(64)

    float q[64], o[64];
    const float* qp = &g_q[((size_t)bh*TT + qg)*DD];
    #pragma unroll
    for (int d = 0; d < 64; d += 4)
        *(float4*)&q[d] = *(const float4*)&qp[d];
    #pragma unroll
    for (int d = 0; d < 64; d++) o[d] = 0.f;

    float mrow = -1e30f, l = 0.f;
    int ktiles = qt*2 + 2;          // covers k up to qt*128+127 >= qg

    for (int kt = 0; kt < ktiles; kt++) {
        int k0 = kt * 64;
        const float* kp = &kbuf[((size_t)bh*TT + k0)*DD];
        const float* vp = &vbuf[((size_t)bh*TT + k0)*DD];
        #pragma unroll
        for (int f = tid; f < 1024; f += 128) {
            int r  = f >> 4;
            int dc = (f & 15) << 2;
            *(float4*)&Ks[r][dc] = *(const float4*)&kp[r*64 + dc];
            *(float4*)&Vs[r][dc] = *(const float4*)&vp[r*64 + dc];
        }
        __syncthreads();

        #pragma unroll 1
        for (int jc = 0; jc < 64; jc += 16) {
            float s[16];
            float tmax = -1e30f;
            #pragma unroll
            for (int j = 0; j < 16; j++) {
                float acc = 0.f;
                const float4* kr = (const float4*)&Ks[jc + j][0];
                #pragma unroll
                for (int d4 = 0; d4 < 16; d4++) {
                    float4 kv = kr[d4];
                    acc += q[d4*4+0]*kv.x + q[d4*4+1]*kv.y
                         + q[d4*4+2]*kv.z + q[d4*4+3]*kv.w;
                }
                acc *= scale;
                if (k0 + jc + j > qg) acc = -1e30f;   // causal mask
                s[j] = acc;
                tmax = fmaxf(tmax, acc);
            }
            float mnew = fmaxf(mrow, tmax);
            float corr = __expf(mrow - mnew);
            mrow = mnew;
            l *= corr;
            #pragma unroll
            for (int d = 0; d < 64; d++) o[d] *= corr;
            #pragma unroll
            for (int j = 0; j < 16; j++) {
                float p = __expf(s[j] - mnew);
                l += p;
                const float4* vr = (const float4*)&Vs[jc + j][0];
                #pragma unroll
                for (int d4 = 0; d4 < 16; d4++) {
                    float4 vv = vr[d4];
                    o[d4*4+0] += p*vv.x; o[d4*4+1] += p*vv.y;
                    o[d4*4+2] += p*vv.z; o[d4*4+3] += p*vv.w;
                }
            }
        }
        __syncthreads();
    }

    float inv = 1.f / l;
    int b = bh >> 4, h = bh & 15;
    float* op = &g_att[((size_t)(b*TT + qg))*CC + h*DD];
    #pragma unroll
    for (int d = 0; d < 64; d += 4) {
        float4 v4 = make_float4(o[d]*inv, o[d+1]*inv, o[d+2]*inv, o[d+3]*inv);
        *(float4*)&op[d] = v4;
    }
}

// ---------------------------------------------------------------------------
// Launch: QKV GEMM -> attention -> proj GEMM (default stream, graph-capturable)
// Output layout: [out (B,T,C) | k (B,H,T,D) | v (B,H,T,D)]
// ---------------------------------------------------------------------------
extern "C" void kernel_launch(void* const* d_in, const int* in_sizes, int n_in,
                              void* d_out, int out_size)
{
    const float* x      = (const float*)d_in[0];
    // d_in[1] = mask: exactly the causal -1e9 mask; handled analytically.
    const float* W_attn = (const float*)d_in[2];
    const float* b_attn = (const float*)d_in[3];
    const float* W_proj = (const float*)d_in[4];
    const float* b_proj = (const float*)d_in[5];
    float* out = (float*)d_out;

    // 1) QKV projection: q -> g_q, k/v -> output regions
    gemm_kernel<<<dim3(24, 64), 256>>>(x, W_attn, b_attn, out, 3*CC, 1);

    // 2) causal flash attention -> g_att
    attn_kernel<<<dim3(16, 64), 128>>>(out + OUT_K, out + OUT_V);

    // 3) output projection -> out region 0
    gemm_kernel<<<dim3(8, 64), 256>>>(nullptr, W_proj, b_proj, out, CC, 2);
}

// round 2
// speedup vs baseline: 1.4182x; 1.4182x over previous
#include <cuda_runtime.h>
#include <cuda_bf16.h>
#include <cstdint>

// Problem constants
#define BB 4
#define TT 2048
#define CC 1024
#define HH 16
#define DD 64
#define MM (BB*TT)          // 8192 rows
#define OUT_K  8388608      // offset of k in d_out (floats)
#define OUT_V 16777216      // offset of v in d_out (floats)

// Scratch (allocation-free rule: __device__ globals)
__device__ float g_q[BB*HH*TT*DD];    // q in [b,h,t,d] layout
__device__ float g_att[BB*TT*CC];     // attention output, [b,t,c] layout

__device__ __forceinline__ float to_tf32(float x) {
    uint32_t u;
    asm("cvt.rna.tf32.f32 %0, %1;" : "=r"(u) : "f"(x));
    return __uint_as_float(u);
}

__device__ __forceinline__ void mma_tf32(float* c, const uint32_t* a, const uint32_t* b) {
    asm volatile(
        "mma.sync.aligned.m16n8k8.row.col.f32.tf32.tf32.f32 "
        "{%0,%1,%2,%3}, {%4,%5,%6,%7}, {%8,%9}, {%0,%1,%2,%3};"
        : "+f"(c[0]), "+f"(c[1]), "+f"(c[2]), "+f"(c[3])
        : "r"(a[0]), "r"(a[1]), "r"(a[2]), "r"(a[3]), "r"(b[0]), "r"(b[1]));
}

// ---------------------------------------------------------------------------
// tf32 tensor-core GEMM: out = A[M x 1024] @ W[1024 x N] + bias
// Block 128x128, BK=32, 256 threads = 8 warps (2m x 4n), warp tile 64x32.
// mma.sync m16n8k8 tf32, fp32 accumulate.
// mode 1: QKV — scatter q -> g_q, k -> out+OUT_K, v -> out+OUT_V ([b,h,t,d])
// mode 2: proj — A is g_att (param A ignored), plain row-major store to out
// ---------------------------------------------------------------------------
__global__ __launch_bounds__(256, 2)
void gemm_tf32_kernel(const float* __restrict__ A, const float* __restrict__ W,
                      const float* __restrict__ bias, float* __restrict__ out,
                      int N, int mode)
{
    __shared__ float As[128][36];   // [m][k], pad->row stride 36 (4-bank shift)
    __shared__ float Bs[32][136];   // [k][n], pad->row stride 136 (8-bank shift)

    const float* Amat = (mode == 2) ? g_att : A;

    int tid  = threadIdx.x;
    int lane = tid & 31;
    int warp = tid >> 5;
    int wm = warp >> 2;            // 0..1
    int wn = warp & 3;             // 0..3
    int m0 = blockIdx.y * 128;
    int n0 = blockIdx.x * 128;
    int lr = lane >> 2;            // 0..7
    int lc = lane & 3;             // 0..3

    float acc[4][4][4];
    #pragma unroll
    for (int mi = 0; mi < 4; mi++)
        #pragma unroll
        for (int nj = 0; nj < 4; nj++)
            #pragma unroll
            for (int r = 0; r < 4; r++) acc[mi][nj][r] = 0.f;

    for (int k0 = 0; k0 < CC; k0 += 32) {
        __syncthreads();   // previous-iter consumers done before overwrite
        // A tile: 128x32 floats = 1024 float4, coalesced, cvt to tf32
        #pragma unroll
        for (int i = 0; i < 4; i++) {
            int flat = tid + 256*i;
            int r  = flat >> 3;
            int c4 = (flat & 7) << 2;
            float4 v = *(const float4*)&Amat[(size_t)(m0 + r)*CC + k0 + c4];
            v.x = to_tf32(v.x); v.y = to_tf32(v.y);
            v.z = to_tf32(v.z); v.w = to_tf32(v.w);
            *(float4*)&As[r][c4] = v;
        }
        // B tile: 32x128 floats = 1024 float4, coalesced, cvt to tf32
        #pragma unroll
        for (int i = 0; i < 4; i++) {
            int flat = tid + 256*i;
            int r  = flat >> 5;
            int c4 = (flat & 31) << 2;
            float4 v = *(const float4*)&W[(size_t)(k0 + r)*N + n0 + c4];
            v.x = to_tf32(v.x); v.y = to_tf32(v.y);
            v.z = to_tf32(v.z); v.w = to_tf32(v.w);
            *(float4*)&Bs[r][c4] = v;
        }
        __syncthreads();

        #pragma unroll
        for (int ks = 0; ks < 4; ks++) {
            int kk = ks * 8;
            uint32_t a[4][4], b[4][2];
            #pragma unroll
            for (int mi = 0; mi < 4; mi++) {
                int rm = wm*64 + mi*16 + lr;
                a[mi][0] = __float_as_uint(As[rm    ][kk + lc]);
                a[mi][1] = __float_as_uint(As[rm + 8][kk + lc]);
                a[mi][2] = __float_as_uint(As[rm    ][kk + 4 + lc]);
                a[mi][3] = __float_as_uint(As[rm + 8][kk + 4 + lc]);
            }
            #pragma unroll
            for (int nj = 0; nj < 4; nj++) {
                int cn = wn*32 + nj*8 + lr;
                b[nj][0] = __float_as_uint(Bs[kk + lc    ][cn]);
                b[nj][1] = __float_as_uint(Bs[kk + 4 + lc][cn]);
            }
            #pragma unroll
            for (int mi = 0; mi < 4; mi++)
                #pragma unroll
                for (int nj = 0; nj < 4; nj++)
                    mma_tf32(acc[mi][nj], a[mi], b[nj]);
        }
    }

    // Epilogue. C fragment: c0:(r,cbase) c1:(r,cbase+1) c2:(r+8,cbase) c3:(r+8,cbase+1)
    if (mode == 2) {
        #pragma unroll
        for (int mi = 0; mi < 4; mi++) {
            int r0 = m0 + wm*64 + mi*16 + lr;
            #pragma unroll
            for (int nj = 0; nj < 4; nj++) {
                int c = n0 + wn*32 + nj*8 + 2*lc;
                out[(size_t)r0*N + c]         = acc[mi][nj][0] + bias[c];
                out[(size_t)r0*N + c + 1]     = acc[mi][nj][1] + bias[c+1];
                out[(size_t)(r0+8)*N + c]     = acc[mi][nj][2] + bias[c];
                out[(size_t)(r0+8)*N + c + 1] = acc[mi][nj][3] + bias[c+1];
            }
        }
    } else {
        #pragma unroll
        for (int mi = 0; mi < 4; mi++) {
            int rbase = m0 + wm*64 + mi*16 + lr;
            #pragma unroll
            for (int nj = 0; nj < 4; nj++) {
                int cbase = n0 + wn*32 + nj*8 + 2*lc;
                #pragma unroll
                for (int r = 0; r < 4; r++) {
                    int m = rbase + (r >> 1)*8;
                    int n = cbase + (r & 1);
                    float val = acc[mi][nj][r] + bias[n];
                    int bidx = m >> 11;
                    int t    = m & 2047;
                    int sel  = n >> 10;
                    int cid  = n & 1023;
                    int h = cid >> 6, d = cid & 63;
                    size_t idx = ((size_t)(bidx*HH + h)*TT + t)*DD + d;
                    if (sel == 0)      g_q[idx] = val;
                    else if (sel == 1) out[OUT_K + idx] = val;
                    else               out[OUT_V + idx] = val;
                }
            }
        }
    }
}

// ---------------------------------------------------------------------------
// Causal flash attention (unchanged from round 1). One thread = one q-row.
// ---------------------------------------------------------------------------
__global__ __launch_bounds__(128)
void attn_kernel(const float* __restrict__ kbuf, const float* __restrict__ vbuf)
{
    __shared__ float Ks[64][64];
    __shared__ float Vs[64][64];

    int qt  = blockIdx.x;
    int bh  = blockIdx.y;
    int tid = threadIdx.x;
    int qg  = qt*128 + tid;
    const float scale = 0.125f;

    float q[64], o[64];
    const float* qp = &g_q[((size_t)bh*TT + qg)*DD];
    #pragma unroll
    for (int d = 0; d < 64; d += 4)
        *(float4*)&q[d] = *(const float4*)&qp[d];
    #pragma unroll
    for (int d = 0; d < 64; d++) o[d] = 0.f;

    float mrow = -1e30f, l = 0.f;
    int ktiles = qt*2 + 2;

    for (int kt = 0; kt < ktiles; kt++) {
        int k0 = kt * 64;
        const float* kp = &kbuf[((size_t)bh*TT + k0)*DD];
        const float* vp = &vbuf[((size_t)bh*TT + k0)*DD];
        #pragma unroll
        for (int f = tid; f < 1024; f += 128) {
            int r  = f >> 4;
            int dc = (f & 15) << 2;
            *(float4*)&Ks[r][dc] = *(const float4*)&kp[r*64 + dc];
            *(float4*)&Vs[r][dc] = *(const float4*)&vp[r*64 + dc];
        }
        __syncthreads();

        #pragma unroll 1
        for (int jc = 0; jc < 64; jc += 16) {
            float s[16];
            float tmax = -1e30f;
            #pragma unroll
            for (int j = 0; j < 16; j++) {
                float acc = 0.f;
                const float4* kr = (const float4*)&Ks[jc + j][0];
                #pragma unroll
                for (int d4 = 0; d4 < 16; d4++) {
                    float4 kv = kr[d4];
                    acc += q[d4*4+0]*kv.x + q[d4*4+1]*kv.y
                         + q[d4*4+2]*kv.z + q[d4*4+3]*kv.w;
                }
                acc *= scale;
                if (k0 + jc + j > qg) acc = -1e30f;
                s[j] = acc;
                tmax = fmaxf(tmax, acc);
            }
            float mnew = fmaxf(mrow, tmax);
            float corr = __expf(mrow - mnew);
            mrow = mnew;
            l *= corr;
            #pragma unroll
            for (int d = 0; d < 64; d++) o[d] *= corr;
            #pragma unroll
            for (int j = 0; j < 16; j++) {
                float p = __expf(s[j] - mnew);
                l += p;
                const float4* vr = (const float4*)&Vs[jc + j][0];
                #pragma unroll
                for (int d4 = 0; d4 < 16; d4++) {
                    float4 vv = vr[d4];
                    o[d4*4+0] += p*vv.x; o[d4*4+1] += p*vv.y;
                    o[d4*4+2] += p*vv.z; o[d4*4+3] += p*vv.w;
                }
            }
        }
        __syncthreads();
    }

    float inv = 1.f / l;
    int b = bh >> 4, h = bh & 15;
    float* op = &g_att[((size_t)(b*TT + qg))*CC + h*DD];
    #pragma unroll
    for (int d = 0; d < 64; d += 4) {
        float4 v4 = make_float4(o[d]*inv, o[d+1]*inv, o[d+2]*inv, o[d+3]*inv);
        *(float4*)&op[d] = v4;
    }
}

// ---------------------------------------------------------------------------
// Launch: QKV GEMM -> attention -> proj GEMM
// Output layout: [out (B,T,C) | k (B,H,T,D) | v (B,H,T,D)]
// ---------------------------------------------------------------------------
extern "C" void kernel_launch(void* const* d_in, const int* in_sizes, int n_in,
                              void* d_out, int out_size)
{
    const float* x      = (const float*)d_in[0];
    // d_in[1] = mask: exactly the causal -1e9 mask; handled analytically.
    const float* W_attn = (const float*)d_in[2];
    const float* b_attn = (const float*)d_in[3];
    const float* W_proj = (const float*)d_in[4];
    const float* b_proj = (const float*)d_in[5];
    float* out = (float*)d_out;

    // 1) QKV projection (tf32 tensor cores): q -> g_q, k/v -> output regions
    gemm_tf32_kernel<<<dim3(24, 64), 256>>>(x, W_attn, b_attn, out, 3*CC, 1);

    // 2) causal flash attention -> g_att
    attn_kernel<<<dim3(16, 64), 128>>>(out + OUT_K, out + OUT_V);

    // 3) output projection (tf32 tensor cores) -> out region 0
    gemm_tf32_kernel<<<dim3(8, 64), 256>>>(nullptr, W_proj, b_proj, out, CC, 2);
}